// round 10
// baseline (speedup 1.0000x reference)
#include <cuda_runtime.h>
#include <math.h>
#include <stdint.h>

// DWCE loss — persistent CTAs + 2-deep cp.async.bulk pipeline, balanced grid.
// pred: [8,16,512,512] f32, target: [8,512,512] int32, out: scalar f32.
// R10: 64 CTAs/image x exactly 16 tiles (no count imbalance); target-logit
// gather via dynamic LDS instead of a 16-way select chain; overflow-safe
// counter fold.

constexpr int C    = 16;
constexpr int NIMG = 8;
constexpr int HW   = 512 * 512;
constexpr int TPB  = 128;
constexpr int TILE = 256;                       // pixels per tile
constexpr int PPT  = TILE / TPB;                // 2 (float2)
constexpr int TILES_PER_IMG = HW / TILE;        // 1024
constexpr int CTAS_PER_IMG  = 64;
constexpr int TILES_PER_CTA = TILES_PER_IMG / CTAS_PER_IMG;  // 16 exactly
constexpr int GRID = NIMG * CTAS_PER_IMG;       // 512 (single wave)
constexpr unsigned TILE_BYTES = (C + 1) * TILE * 4;   // 17408

__device__ float        g_S[NIMG * C];
__device__ float        g_cnt[NIMG * C];
__device__ unsigned int g_done;

__device__ __forceinline__ uint32_t smem_u32(const void* p) {
    return (uint32_t)__cvta_generic_to_shared(p);
}

__global__ void __launch_bounds__(TPB, 6) dwce_fused_kernel(
    const float* __restrict__ pred,
    const int* __restrict__ target,
    float* __restrict__ out)
{
    __shared__ __align__(16) float buf[2][C][TILE];   // 32 KB
    __shared__ __align__(16) int   tgtb[2][TILE];     // 2 KB
    __shared__ __align__(8)  unsigned long long mbar[2];
    __shared__ float sS[C];
    __shared__ float sN[C];
    __shared__ float swcl[C];
    __shared__ float sratio[NIMG];
    __shared__ bool  is_last;

    const int tid  = threadIdx.x;
    const int lane = tid & 31;
    const int n    = blockIdx.x / CTAS_PER_IMG;
    const int slot = blockIdx.x % CTAS_PER_IMG;

    const float* img_pred = pred   + (size_t)n * C * HW;
    const int*   img_tgt  = target + (size_t)n * HW;

    if (tid == 0) {
        asm volatile("mbarrier.init.shared.b64 [%0], %1;" :: "r"(smem_u32(&mbar[0])), "r"(1) : "memory");
        asm volatile("mbarrier.init.shared.b64 [%0], %1;" :: "r"(smem_u32(&mbar[1])), "r"(1) : "memory");
    }
    if (tid < C) { sS[tid] = 0.0f; sN[tid] = 0.0f; }
    __syncthreads();

    // thread-0 tile fetch into stage s; iteration i maps to tile slot + i*64
    auto fetch = [&](int i, int s) {
        const int t = slot + i * CTAS_PER_IMG;
        const uint32_t mb = smem_u32(&mbar[s]);
        asm volatile("mbarrier.arrive.expect_tx.shared.b64 _, [%0], %1;"
                     :: "r"(mb), "r"(TILE_BYTES) : "memory");
#pragma unroll
        for (int ch = 0; ch < C; ch++) {
            asm volatile(
                "cp.async.bulk.shared::cluster.global.mbarrier::complete_tx::bytes "
                "[%0], [%1], %2, [%3];"
                :: "r"(smem_u32(&buf[s][ch][0])),
                   "l"(img_pred + (size_t)ch * HW + (size_t)t * TILE),
                   "r"((unsigned)(TILE * 4)), "r"(mb) : "memory");
        }
        asm volatile(
            "cp.async.bulk.shared::cluster.global.mbarrier::complete_tx::bytes "
            "[%0], [%1], %2, [%3];"
            :: "r"(smem_u32(&tgtb[s][0])),
               "l"(img_tgt + (size_t)t * TILE),
               "r"((unsigned)(TILE * 4)), "r"(mb) : "memory");
    };

    if (tid == 0) fetch(0, 0);

    // per-thread packed class counters (16 classes x 8-bit in 4 u32);
    // max 16 tiles x 2 px = 32 per field.
    unsigned int c0 = 0, c1 = 0, c2 = 0, c3 = 0;

    for (int i = 0; i < TILES_PER_CTA; i++) {
        const int s = i & 1;
        if (tid == 0 && (i + 1) < TILES_PER_CTA) fetch(i + 1, s ^ 1);

        // wait stage s, parity = (i>>1)&1
        {
            const uint32_t mb = smem_u32(&mbar[s]);
            const uint32_t par = (i >> 1) & 1;
            uint32_t done;
            do {
                asm volatile(
                    "{\n\t.reg .pred p;\n\t"
                    "mbarrier.try_wait.parity.acquire.cta.shared::cta.b64 p, [%1], %2, 0x989680;\n\t"
                    "selp.b32 %0, 1, 0, p;\n\t}"
                    : "=r"(done) : "r"(mb), "r"(par) : "memory");
            } while (!done);
        }

        const int2 tv = *reinterpret_cast<const int2*>(&tgtb[s][tid * PPT]);
        const int t0 = tv.x & 15, t1 = tv.y & 15;

        {
            const unsigned int inc0 = 1u << ((t0 & 3) * 8);
            const int w0 = t0 >> 2;
            c0 += (w0 == 0) ? inc0 : 0u;  c1 += (w0 == 1) ? inc0 : 0u;
            c2 += (w0 == 2) ? inc0 : 0u;  c3 += (w0 == 3) ? inc0 : 0u;
            const unsigned int inc1 = 1u << ((t1 & 3) * 8);
            const int w1 = t1 >> 2;
            c0 += (w1 == 0) ? inc1 : 0u;  c1 += (w1 == 1) ? inc1 : 0u;
            c2 += (w1 == 2) ? inc1 : 0u;  c3 += (w1 == 3) ? inc1 : 0u;
        }

        float sx = 0.f, sy = 0.f;
#pragma unroll
        for (int ch = 0; ch < C; ch++) {
            const float2 v = *reinterpret_cast<const float2*>(&buf[s][ch][tid * PPT]);
            sx += __expf(v.x);
            sy += __expf(v.y);
        }
        // target logits via dynamic LDS (row stride 256 floats -> bank-clean)
        const float vtx = buf[s][t0][tid * PPT];
        const float vty = buf[s][t1][tid * PPT + 1];

        atomicAdd(&sS[t0], vtx - __logf(sx));
        atomicAdd(&sS[t1], vty - __logf(sy));

        __syncthreads();   // compute done before this buffer is refetched
    }

    // overflow-safe counter fold: unpack each class, REDUX, lane cl keeps class cl
    {
        unsigned int my = 0;
#pragma unroll
        for (int cl = 0; cl < C; cl++) {
            const unsigned int pk = (cl < 4) ? c0 : (cl < 8) ? c1 : (cl < 12) ? c2 : c3;
            const unsigned int v  = (pk >> ((cl & 3) * 8)) & 0xFFu;
            const unsigned int tot = __reduce_add_sync(0xffffffffu, v);
            if (lane == cl) my = tot;
        }
        if (lane < C) atomicAdd(&sN[lane], (float)my);
    }
    __syncthreads();

    if (tid < C) {
        atomicAdd(&g_S[n * C + tid],   sS[tid]);
        atomicAdd(&g_cnt[n * C + tid], sN[tid]);
    }

    // ---- last-block finalize ----
    __threadfence();
    if (tid == 0) {
        const unsigned int d = atomicAdd(&g_done, 1u);
        is_last = (d == (unsigned int)(GRID - 1));
    }
    __syncthreads();
    if (!is_last) return;

    if (tid < C) {
        float tot = 0.0f;
#pragma unroll
        for (int im = 0; im < NIMG; im++) tot += __ldcg(&g_cnt[im * C + tid]);
        swcl[tid] = (tot > 0.0f) ? (1.0f / (tot * (float)C)) : 0.0f;
    }
    __syncthreads();

    if (tid < NIMG) {
        float num = 0.0f, den = 0.0f;
#pragma unroll
        for (int cl = 0; cl < C; cl++) {
            const float w = swcl[cl];
            num += __ldcg(&g_S[tid * C + cl])   * w;
            den += __ldcg(&g_cnt[tid * C + cl]) * w;
        }
        sratio[tid] = num / den;
    }
    __syncthreads();

    if (tid == 0) {
        float acc = 0.0f;
#pragma unroll
        for (int im = 0; im < NIMG; im++) acc += sratio[im];
        out[0] = -acc / (float)NIMG;
        g_done = 0;
    }

    // Reset scratch for the next graph replay (TPB == 128 == NIMG*C).
    g_S[tid]   = 0.0f;
    g_cnt[tid] = 0.0f;
}

extern "C" void kernel_launch(void* const* d_in, const int* in_sizes, int n_in,
                              void* d_out, int out_size) {
    const float* pred   = (const float*)d_in[0];
    const int*   target = (const int*)d_in[1];
    float* out = (float*)d_out;

    dwce_fused_kernel<<<GRID, TPB>>>(pred, target, out);
}

// round 11
// speedup vs baseline: 1.0009x; 1.0009x over previous
#include <cuda_runtime.h>
#include <math.h>
#include <stdint.h>

// DWCE loss — persistent CTAs, 4-deep cp.async.bulk ring, mbarrier-only sync.
// pred: [8,16,512,512] f32, target: [8,512,512] int32, out: scalar f32.
// R11: GRID=888 (6 CTAs/SM) restored; TILE=128 px, DEPTH=4 (3 tiles in flight
// per CTA); per-stage empty barriers replace the per-iteration __syncthreads.

constexpr int C     = 16;
constexpr int NIMG  = 8;
constexpr int HW    = 512 * 512;
constexpr int TPB   = 128;
constexpr int TILE  = 128;                      // pixels per tile (1 px/thread)
constexpr int DEPTH = 4;                        // ring stages
constexpr int TILES_PER_IMG = HW / TILE;        // 2048
constexpr int CTAS_PER_IMG  = 111;
constexpr int GRID = NIMG * CTAS_PER_IMG;       // 888 = 6 x 148
constexpr unsigned TILE_BYTES = (C + 1) * TILE * 4;   // 8704

__device__ float        g_S[NIMG * C];
__device__ float        g_cnt[NIMG * C];
__device__ unsigned int g_done;

__device__ __forceinline__ uint32_t smem_u32(const void* p) {
    return (uint32_t)__cvta_generic_to_shared(p);
}

__device__ __forceinline__ void mbar_wait(uint32_t mb, uint32_t par) {
    uint32_t done;
    do {
        asm volatile(
            "{\n\t.reg .pred p;\n\t"
            "mbarrier.try_wait.parity.acquire.cta.shared::cta.b64 p, [%1], %2, 0x989680;\n\t"
            "selp.b32 %0, 1, 0, p;\n\t}"
            : "=r"(done) : "r"(mb), "r"(par) : "memory");
    } while (!done);
}

__global__ void __launch_bounds__(TPB, 6) dwce_fused_kernel(
    const float* __restrict__ pred,
    const int* __restrict__ target,
    float* __restrict__ out)
{
    __shared__ __align__(16) float buf[DEPTH][C][TILE];   // 32 KB
    __shared__ __align__(16) int   tgtb[DEPTH][TILE];     // 2 KB
    __shared__ __align__(8)  unsigned long long full_mb[DEPTH];
    __shared__ __align__(8)  unsigned long long empty_mb[DEPTH];
    __shared__ float sS[C];
    __shared__ float sN[C];
    __shared__ float swcl[C];
    __shared__ float sratio[NIMG];
    __shared__ bool  is_last;

    const int tid  = threadIdx.x;
    const int lane = tid & 31;
    const int n    = blockIdx.x / CTAS_PER_IMG;
    const int slot = blockIdx.x % CTAS_PER_IMG;
    const int niter = (TILES_PER_IMG - slot - 1) / CTAS_PER_IMG + 1;  // 18 or 19

    const float* img_pred = pred   + (size_t)n * C * HW;
    const int*   img_tgt  = target + (size_t)n * HW;

    if (tid == 0) {
#pragma unroll
        for (int s = 0; s < DEPTH; s++) {
            asm volatile("mbarrier.init.shared.b64 [%0], %1;"
                         :: "r"(smem_u32(&full_mb[s])), "r"(1) : "memory");
            asm volatile("mbarrier.init.shared.b64 [%0], %1;"
                         :: "r"(smem_u32(&empty_mb[s])), "r"(TPB) : "memory");
        }
    }
    if (tid < C) { sS[tid] = 0.0f; sN[tid] = 0.0f; }
    __syncthreads();

    // thread-0 fetch of iteration j into stage j%DEPTH (waits empty first)
    auto fetch = [&](int j) {
        const int s = j & (DEPTH - 1);
        const uint32_t epar = 1u ^ ((j >> 2) & 1u);     // use-k parity, first use immediate
        mbar_wait(smem_u32(&empty_mb[s]), epar);
        const uint32_t mb = smem_u32(&full_mb[s]);
        asm volatile("mbarrier.arrive.expect_tx.shared.b64 _, [%0], %1;"
                     :: "r"(mb), "r"(TILE_BYTES) : "memory");
        const int t = slot + j * CTAS_PER_IMG;
        const float* src = img_pred + (size_t)t * TILE;
#pragma unroll
        for (int ch = 0; ch < C; ch++) {
            asm volatile(
                "cp.async.bulk.shared::cluster.global.mbarrier::complete_tx::bytes "
                "[%0], [%1], %2, [%3];"
                :: "r"(smem_u32(&buf[s][ch][0])),
                   "l"(src + (size_t)ch * HW),
                   "r"((unsigned)(TILE * 4)), "r"(mb) : "memory");
        }
        asm volatile(
            "cp.async.bulk.shared::cluster.global.mbarrier::complete_tx::bytes "
            "[%0], [%1], %2, [%3];"
            :: "r"(smem_u32(&tgtb[s][0])),
               "l"(img_tgt + (size_t)t * TILE),
               "r"((unsigned)(TILE * 4)), "r"(mb) : "memory");
    };

    // prologue: put DEPTH-1 tiles in flight
    if (tid == 0) {
#pragma unroll
        for (int j = 0; j < DEPTH - 1; j++)
            if (j < niter) fetch(j);
    }

    // per-thread packed class counters (16 classes x 8-bit in 4 u32); max 19.
    unsigned int c0 = 0, c1 = 0, c2 = 0, c3 = 0;

    for (int i = 0; i < niter; i++) {
        const int s = i & (DEPTH - 1);
        if (tid == 0 && (i + DEPTH - 1) < niter) fetch(i + DEPTH - 1);

        mbar_wait(smem_u32(&full_mb[s]), (i >> 2) & 1u);

        const int t0 = tgtb[s][tid] & 15;
        {
            const unsigned int inc = 1u << ((t0 & 3) * 8);
            const int w = t0 >> 2;
            c0 += (w == 0) ? inc : 0u;  c1 += (w == 1) ? inc : 0u;
            c2 += (w == 2) ? inc : 0u;  c3 += (w == 3) ? inc : 0u;
        }

        float sum = 0.f;
#pragma unroll
        for (int ch = 0; ch < C; ch++) sum += __expf(buf[s][ch][tid]);
        const float vt = buf[s][t0][tid];   // dyn LDS; stride 128 floats -> bank-clean

        atomicAdd(&sS[t0], vt - __logf(sum));

        // release this stage for refetch
        asm volatile("mbarrier.arrive.shared.b64 _, [%0];"
                     :: "r"(smem_u32(&empty_mb[s])) : "memory");
    }

    __syncthreads();   // all sS atomics + counters done

    // overflow-safe counter fold: unpack each class, REDUX, lane cl keeps class cl
    {
        unsigned int my = 0;
#pragma unroll
        for (int cl = 0; cl < C; cl++) {
            const unsigned int pk = (cl < 4) ? c0 : (cl < 8) ? c1 : (cl < 12) ? c2 : c3;
            const unsigned int v  = (pk >> ((cl & 3) * 8)) & 0xFFu;
            const unsigned int tot = __reduce_add_sync(0xffffffffu, v);
            if (lane == cl) my = tot;
        }
        if (lane < C) atomicAdd(&sN[lane], (float)my);
    }
    __syncthreads();

    if (tid < C) {
        atomicAdd(&g_S[n * C + tid],   sS[tid]);
        atomicAdd(&g_cnt[n * C + tid], sN[tid]);
    }

    // ---- last-block finalize ----
    __threadfence();
    if (tid == 0) {
        const unsigned int d = atomicAdd(&g_done, 1u);
        is_last = (d == (unsigned int)(GRID - 1));
    }
    __syncthreads();
    if (!is_last) return;

    if (tid < C) {
        float tot = 0.0f;
#pragma unroll
        for (int im = 0; im < NIMG; im++) tot += __ldcg(&g_cnt[im * C + tid]);
        swcl[tid] = (tot > 0.0f) ? (1.0f / (tot * (float)C)) : 0.0f;
    }
    __syncthreads();

    if (tid < NIMG) {
        float num = 0.0f, den = 0.0f;
#pragma unroll
        for (int cl = 0; cl < C; cl++) {
            const float w = swcl[cl];
            num += __ldcg(&g_S[tid * C + cl])   * w;
            den += __ldcg(&g_cnt[tid * C + cl]) * w;
        }
        sratio[tid] = num / den;
    }
    __syncthreads();

    if (tid == 0) {
        float acc = 0.0f;
#pragma unroll
        for (int im = 0; im < NIMG; im++) acc += sratio[im];
        out[0] = -acc / (float)NIMG;
        g_done = 0;
    }

    // Reset scratch for the next graph replay (TPB == 128 == NIMG*C).
    g_S[tid]   = 0.0f;
    g_cnt[tid] = 0.0f;
}

extern "C" void kernel_launch(void* const* d_in, const int* in_sizes, int n_in,
                              void* d_out, int out_size) {
    const float* pred   = (const float*)d_in[0];
    const int*   target = (const int*)d_in[1];
    float* out = (float*)d_out;

    dwce_fused_kernel<<<GRID, TPB>>>(pred, target, out);
}

// round 12
// speedup vs baseline: 1.0626x; 1.0616x over previous
#include <cuda_runtime.h>
#include <math.h>
#include <stdint.h>

// DWCE loss — persistent CTAs, 3-deep cp.async.bulk ring (dynamic smem).
// pred: [8,16,512,512] f32, target: [8,512,512] int32, out: scalar f32.
// R12: R9 skeleton (TILE=256, __syncthreads release, 1KB copies) + DEPTH=3
// (2 tiles in flight per CTA), 4 CTAs/SM x 148 = 592 CTAs, dynamic-LDS gather.

constexpr int C     = 16;
constexpr int NIMG  = 8;
constexpr int HW    = 512 * 512;
constexpr int TPB   = 128;
constexpr int TILE  = 256;                      // pixels per tile (2 px/thread)
constexpr int PPT   = TILE / TPB;               // 2
constexpr int DEPTH = 3;
constexpr int TILES_PER_IMG = HW / TILE;        // 1024
constexpr int CTAS_PER_IMG  = 74;
constexpr int GRID = NIMG * CTAS_PER_IMG;       // 592 = 4 x 148
constexpr unsigned TILE_BYTES = (C + 1) * TILE * 4;       // 17408
constexpr unsigned SMEM_DYN   = DEPTH * TILE_BYTES;       // 52224

__device__ float        g_S[NIMG * C];
__device__ float        g_cnt[NIMG * C];
__device__ unsigned int g_done;

__device__ __forceinline__ uint32_t smem_u32(const void* p) {
    return (uint32_t)__cvta_generic_to_shared(p);
}

__device__ __forceinline__ void mbar_wait(uint32_t mb, uint32_t par) {
    uint32_t done;
    do {
        asm volatile(
            "{\n\t.reg .pred p;\n\t"
            "mbarrier.try_wait.parity.acquire.cta.shared::cta.b64 p, [%1], %2, 0x989680;\n\t"
            "selp.b32 %0, 1, 0, p;\n\t}"
            : "=r"(done) : "r"(mb), "r"(par) : "memory");
    } while (!done);
}

__global__ void __launch_bounds__(TPB, 4) dwce_fused_kernel(
    const float* __restrict__ pred,
    const int* __restrict__ target,
    float* __restrict__ out)
{
    extern __shared__ __align__(16) char dyn_smem[];
    // layout: DEPTH stages of [16 channel rows (256 f32) + 256 i32 targets]
    float* buf  = reinterpret_cast<float*>(dyn_smem);            // [s][ch][TILE]
    auto buf_at = [&](int s, int ch) -> float* {
        return buf + ((size_t)s * (C + 1) + ch) * TILE;
    };
    auto tgt_at = [&](int s) -> int* {
        return reinterpret_cast<int*>(buf + ((size_t)s * (C + 1) + C) * TILE);
    };

    __shared__ __align__(8) unsigned long long full_mb[DEPTH];
    __shared__ float sS[C];
    __shared__ float sN[C];
    __shared__ float swcl[C];
    __shared__ float sratio[NIMG];
    __shared__ bool  is_last;

    const int tid  = threadIdx.x;
    const int lane = tid & 31;
    const int n    = blockIdx.x / CTAS_PER_IMG;
    const int slot = blockIdx.x % CTAS_PER_IMG;
    const int niter = (TILES_PER_IMG - slot - 1) / CTAS_PER_IMG + 1;  // 13 or 14

    const float* img_pred = pred   + (size_t)n * C * HW;
    const int*   img_tgt  = target + (size_t)n * HW;

    if (tid == 0) {
#pragma unroll
        for (int s = 0; s < DEPTH; s++)
            asm volatile("mbarrier.init.shared.b64 [%0], %1;"
                         :: "r"(smem_u32(&full_mb[s])), "r"(1) : "memory");
    }
    if (tid < C) { sS[tid] = 0.0f; sN[tid] = 0.0f; }
    __syncthreads();

    // thread-0 fetch of iteration j into stage j % DEPTH
    auto fetch = [&](int j) {
        const int s = j % DEPTH;
        const uint32_t mb = smem_u32(&full_mb[s]);
        asm volatile("mbarrier.arrive.expect_tx.shared.b64 _, [%0], %1;"
                     :: "r"(mb), "r"(TILE_BYTES) : "memory");
        const int t = slot + j * CTAS_PER_IMG;
        const float* src = img_pred + (size_t)t * TILE;
#pragma unroll
        for (int ch = 0; ch < C; ch++) {
            asm volatile(
                "cp.async.bulk.shared::cluster.global.mbarrier::complete_tx::bytes "
                "[%0], [%1], %2, [%3];"
                :: "r"(smem_u32(buf_at(s, ch))),
                   "l"(src + (size_t)ch * HW),
                   "r"((unsigned)(TILE * 4)), "r"(mb) : "memory");
        }
        asm volatile(
            "cp.async.bulk.shared::cluster.global.mbarrier::complete_tx::bytes "
            "[%0], [%1], %2, [%3];"
            :: "r"(smem_u32(tgt_at(s))),
               "l"(img_tgt + (size_t)t * TILE),
               "r"((unsigned)(TILE * 4)), "r"(mb) : "memory");
    };

    // prologue: DEPTH-1 = 2 tiles in flight
    if (tid == 0) {
        if (0 < niter) fetch(0);
        if (1 < niter) fetch(1);
    }

    // per-thread packed class counters (16 classes x 8-bit in 4 u32); max 28.
    unsigned int c0 = 0, c1 = 0, c2 = 0, c3 = 0;

    for (int i = 0; i < niter; i++) {
        const int s = i % DEPTH;
        // stage (i+2)%DEPTH was computed at iter i-1 and released by its sync
        if (tid == 0 && (i + 2) < niter) fetch(i + 2);

        mbar_wait(smem_u32(&full_mb[s]), (unsigned)((i / DEPTH) & 1));

        const int* tg = tgt_at(s);
        const int2 tv = *reinterpret_cast<const int2*>(&tg[tid * PPT]);
        const int t0 = tv.x & 15, t1 = tv.y & 15;

        {
            const unsigned int inc0 = 1u << ((t0 & 3) * 8);
            const int w0 = t0 >> 2;
            c0 += (w0 == 0) ? inc0 : 0u;  c1 += (w0 == 1) ? inc0 : 0u;
            c2 += (w0 == 2) ? inc0 : 0u;  c3 += (w0 == 3) ? inc0 : 0u;
            const unsigned int inc1 = 1u << ((t1 & 3) * 8);
            const int w1 = t1 >> 2;
            c0 += (w1 == 0) ? inc1 : 0u;  c1 += (w1 == 1) ? inc1 : 0u;
            c2 += (w1 == 2) ? inc1 : 0u;  c3 += (w1 == 3) ? inc1 : 0u;
        }

        float sx = 0.f, sy = 0.f;
#pragma unroll
        for (int ch = 0; ch < C; ch++) {
            const float2 v = *reinterpret_cast<const float2*>(&buf_at(s, ch)[tid * PPT]);
            sx += __expf(v.x);
            sy += __expf(v.y);
        }
        // target logits via dynamic LDS (row stride 256 floats -> bank-clean)
        const float vtx = buf_at(s, t0)[tid * PPT];
        const float vty = buf_at(s, t1)[tid * PPT + 1];

        atomicAdd(&sS[t0], vtx - __logf(sx));
        atomicAdd(&sS[t1], vty - __logf(sy));

        __syncthreads();   // release stage s for refetch at iter i+1
    }

    // overflow-safe counter fold: unpack each class, REDUX, lane cl keeps class cl
    {
        unsigned int my = 0;
#pragma unroll
        for (int cl = 0; cl < C; cl++) {
            const unsigned int pk = (cl < 4) ? c0 : (cl < 8) ? c1 : (cl < 12) ? c2 : c3;
            const unsigned int v  = (pk >> ((cl & 3) * 8)) & 0xFFu;
            const unsigned int tot = __reduce_add_sync(0xffffffffu, v);
            if (lane == cl) my = tot;
        }
        if (lane < C) atomicAdd(&sN[lane], (float)my);
    }
    __syncthreads();

    if (tid < C) {
        atomicAdd(&g_S[n * C + tid],   sS[tid]);
        atomicAdd(&g_cnt[n * C + tid], sN[tid]);
    }

    // ---- last-block finalize ----
    __threadfence();
    if (tid == 0) {
        const unsigned int d = atomicAdd(&g_done, 1u);
        is_last = (d == (unsigned int)(GRID - 1));
    }
    __syncthreads();
    if (!is_last) return;

    if (tid < C) {
        float tot = 0.0f;
#pragma unroll
        for (int im = 0; im < NIMG; im++) tot += __ldcg(&g_cnt[im * C + tid]);
        swcl[tid] = (tot > 0.0f) ? (1.0f / (tot * (float)C)) : 0.0f;
    }
    __syncthreads();

    if (tid < NIMG) {
        float num = 0.0f, den = 0.0f;
#pragma unroll
        for (int cl = 0; cl < C; cl++) {
            const float w = swcl[cl];
            num += __ldcg(&g_S[tid * C + cl])   * w;
            den += __ldcg(&g_cnt[tid * C + cl]) * w;
        }
        sratio[tid] = num / den;
    }
    __syncthreads();

    if (tid == 0) {
        float acc = 0.0f;
#pragma unroll
        for (int im = 0; im < NIMG; im++) acc += sratio[im];
        out[0] = -acc / (float)NIMG;
        g_done = 0;
    }

    // Reset scratch for the next graph replay (TPB == 128 == NIMG*C).
    g_S[tid]   = 0.0f;
    g_cnt[tid] = 0.0f;
}

extern "C" void kernel_launch(void* const* d_in, const int* in_sizes, int n_in,
                              void* d_out, int out_size) {
    const float* pred   = (const float*)d_in[0];
    const int*   target = (const int*)d_in[1];
    float* out = (float*)d_out;

    static bool attr_set = false;
    if (!attr_set) {
        cudaFuncSetAttribute(dwce_fused_kernel,
                             cudaFuncAttributeMaxDynamicSharedMemorySize, SMEM_DYN);
        attr_set = true;
    }
    dwce_fused_kernel<<<GRID, TPB, SMEM_DYN>>>(pred, target, out);
}